// round 11
// baseline (speedup 1.0000x reference)
#include <cuda_runtime.h>
#include <cuda_fp16.h>
#include <cstdint>
#include <cstddef>

typedef __half f16;
#define DI __device__ __forceinline__

constexpr int Bn = 4, Pn = 1024, Xn = 8192, Cn = 1024;
// symmetric fold: q *= S32, k *= c * S32  ->  q.k carries 1/32 = 1/sqrt(C)
#define S32 0.1767766952966369f

// ---------------- scratch (device globals, no allocation) ----------------
__device__ f16   g_qh[(size_t)Bn * Pn * Cn];
__device__ f16   g_ql[(size_t)Bn * Pn * Cn];   // only read by softmax repair
__device__ f16   g_kh[(size_t)Bn * Xn * Cn];
__device__ f16   g_kl[(size_t)Bn * Xn * Cn];   // only read by softmax repair
__device__ f16   g_v [(size_t)Bn * Xn * Cn];
__device__ f16   g_vt[(size_t)Bn * Cn * Xn];
__device__ f16   g_S [(size_t)Bn * Pn * Xn];   // scores f16 (repaired later)
__device__ f16   g_W [(size_t)Bn * Pn * Xn];

// ---------------- PTX helpers ----------------
DI void cp_async16(uint32_t saddr, const void* gptr) {
    asm volatile("cp.async.cg.shared.global [%0], [%1], 16;\n" :: "r"(saddr), "l"(gptr));
}
DI void cp_commit() { asm volatile("cp.async.commit_group;\n"); }
template <int N> DI void cp_wait() { asm volatile("cp.async.wait_group %0;\n" :: "n"(N)); }

DI void ldsm4(uint32_t addr, uint32_t& r0, uint32_t& r1, uint32_t& r2, uint32_t& r3) {
    asm volatile("ldmatrix.sync.aligned.m8n8.x4.shared.b16 {%0,%1,%2,%3}, [%4];\n"
                 : "=r"(r0), "=r"(r1), "=r"(r2), "=r"(r3) : "r"(addr));
}
DI void mma16816(float c[4], const uint32_t a[4], const uint32_t b[2]) {
    asm volatile(
        "mma.sync.aligned.m16n8k16.row.col.f32.f16.f16.f32 "
        "{%0,%1,%2,%3}, {%4,%5,%6,%7}, {%8,%9}, {%0,%1,%2,%3};\n"
        : "+f"(c[0]), "+f"(c[1]), "+f"(c[2]), "+f"(c[3])
        : "r"(a[0]), "r"(a[1]), "r"(a[2]), "r"(a[3]), "r"(b[0]), "r"(b[1]));
}

// Swizzled byte offset inside a 128-row x 64-col f16 tile (128B rows, SW128 XOR).
DI uint32_t swz(int r, int c8) { return (uint32_t)(r * 128 + ((c8 ^ (r & 7)) << 4)); }

// ---------------- LayerNorm -> f16 (optionally hi/lo split), C = 1024 ----------------
__global__ void __launch_bounds__(256) ln_kernel(
    const float* __restrict__ src, f16* __restrict__ dst_h, f16* __restrict__ dst_l,
    const float* __restrict__ gamma, const float* __restrict__ beta,
    const float* __restrict__ cscale, float sconst)
{
    const int row = blockIdx.x;
    const int t = threadIdx.x;
    const float4* s4 = reinterpret_cast<const float4*>(src) + (size_t)row * 256;
    float4 x = s4[t];
    float sum = x.x + x.y + x.z + x.w;
    float sq  = fmaf(x.x, x.x, fmaf(x.y, x.y, fmaf(x.z, x.z, x.w * x.w)));
#pragma unroll
    for (int o = 16; o; o >>= 1) {
        sum += __shfl_xor_sync(0xffffffffu, sum, o);
        sq  += __shfl_xor_sync(0xffffffffu, sq,  o);
    }
    __shared__ float s_sum[8], s_sq[8];
    if ((t & 31) == 0) { s_sum[t >> 5] = sum; s_sq[t >> 5] = sq; }
    __syncthreads();
    sum = 0.f; sq = 0.f;
#pragma unroll
    for (int i = 0; i < 8; i++) { sum += s_sum[i]; sq += s_sq[i]; }
    const float mu  = sum * (1.f / 1024.f);
    const float var = sq * (1.f / 1024.f) - mu * mu;
    const float rs  = rsqrtf(var + 1e-5f);
    const float sc  = (cscale ? __ldg(cscale + row) : 1.f) * sconst;

    const float4 g = reinterpret_cast<const float4*>(gamma)[t];
    const float4 b = reinterpret_cast<const float4*>(beta)[t];
    float y[4];
    y[0] = ((x.x - mu) * rs * g.x + b.x) * sc;
    y[1] = ((x.y - mu) * rs * g.y + b.y) * sc;
    y[2] = ((x.z - mu) * rs * g.z + b.z) * sc;
    y[3] = ((x.w - mu) * rs * g.w + b.w) * sc;

    __half2 h01 = __floats2half2_rn(y[0], y[1]);
    __half2 h23 = __floats2half2_rn(y[2], y[3]);
    uint2 pk;
    pk.x = *reinterpret_cast<uint32_t*>(&h01);
    pk.y = *reinterpret_cast<uint32_t*>(&h23);
    reinterpret_cast<uint2*>(dst_h + (size_t)row * 1024)[t] = pk;

    if (dst_l) {
        float l0 = y[0] - __half2float(__low2half(h01));
        float l1 = y[1] - __half2float(__high2half(h01));
        float l2 = y[2] - __half2float(__low2half(h23));
        float l3 = y[3] - __half2float(__high2half(h23));
        __half2 l01 = __floats2half2_rn(l0, l1);
        __half2 l23 = __floats2half2_rn(l2, l3);
        uint2 pl;
        pl.x = *reinterpret_cast<uint32_t*>(&l01);
        pl.y = *reinterpret_cast<uint32_t*>(&l23);
        reinterpret_cast<uint2*>(dst_l + (size_t)row * 1024)[t] = pl;
    }
}

// ---------------- f16 transpose: [b][X][C] -> [b][C][X] ----------------
__global__ void transpose_kernel(const f16* __restrict__ src, f16* __restrict__ dst)
{
    __shared__ f16 tile[32][34];
    const int b = blockIdx.z;
    const int x0 = blockIdx.x << 5, c0 = blockIdx.y << 5;
    const f16* s = src + ((size_t)b * Xn + x0) * Cn + c0;
#pragma unroll
    for (int j = 0; j < 4; j++)
        tile[threadIdx.y + j * 8][threadIdx.x] =
            s[(size_t)(threadIdx.y + j * 8) * Cn + threadIdx.x];
    __syncthreads();
    f16* d = dst + ((size_t)b * Cn + c0) * Xn + x0;
#pragma unroll
    for (int j = 0; j < 4; j++)
        d[(size_t)(threadIdx.y + j * 8) * Xn + threadIdx.x] =
            tile[threadIdx.x][threadIdx.y + j * 8];
}

// ---------------- tiled f16 GEMM: 128x128 CTA tile, K-tiles of 64 ----------------
// EPI 0: store f16 scores.  EPI 1: store fp32 (acc + Res).
template <int STAGES, int EPI>
__global__ void __launch_bounds__(256, 2) gemm_kernel(
    const f16* __restrict__ A0, const f16* __restrict__ B0,
    void* __restrict__ Co, const float* __restrict__ Res,
    int M, int N, int K)
{
    extern __shared__ __align__(1024) char smem_raw[];
    constexpr int TILE = 16384;                       // 128x64 f16
    constexpr int SS   = 2 * TILE;
    const int tid = threadIdx.x, lane = tid & 31, warp = tid >> 5;
    const int wm = warp & 3, wn = warp >> 2;          // 4 x 2 warp grid
    const int bN = blockIdx.x, bM = blockIdx.y;

    const f16* Ap = A0 + (size_t)bM * 128 * K;
    const f16* Bp = B0 + (size_t)bN * 128 * K;

    const uint32_t sb = (uint32_t)__cvta_generic_to_shared(smem_raw);
    const int KT = K >> 6;

    auto fill = [&](int t) {
        const int k0 = t * 64;
        const uint32_t base = sb + (uint32_t)(t % STAGES) * SS;
#pragma unroll
        for (int i = 0; i < 4; i++) {
            int idx = tid + i * 256; int r = idx >> 3, c8 = idx & 7;
            cp_async16(base + swz(r, c8), Ap + (size_t)r * K + k0 + c8 * 8);
        }
#pragma unroll
        for (int i = 0; i < 4; i++) {
            int idx = tid + i * 256; int r = idx >> 3, c8 = idx & 7;
            cp_async16(base + TILE + swz(r, c8), Bp + (size_t)r * K + k0 + c8 * 8);
        }
        cp_commit();
    };

    float acc[2][8][4];
#pragma unroll
    for (int mt = 0; mt < 2; mt++)
#pragma unroll
        for (int nt = 0; nt < 8; nt++)
#pragma unroll
            for (int i = 0; i < 4; i++) acc[mt][nt][i] = 0.f;

#pragma unroll
    for (int t = 0; t < STAGES - 1; t++) fill(t);

    for (int kt = 0; kt < KT; kt++) {
        cp_wait<STAGES - 2>();
        __syncthreads();
        { const int t = kt + STAGES - 1; if (t < KT) fill(t); else cp_commit(); }

        const uint32_t base = sb + (uint32_t)(kt % STAGES) * SS;
        const uint32_t sA = base;
        const uint32_t sB = base + TILE;
#pragma unroll
        for (int kk = 0; kk < 4; kk++) {
            uint32_t bh[8][2];
#pragma unroll
            for (int np = 0; np < 4; np++) {
                int r = wn * 64 + np * 16 + ((lane >> 4) << 3) + (lane & 7);
                int c8 = kk * 2 + ((lane >> 3) & 1);
                ldsm4(sB + swz(r, c8), bh[2 * np][0], bh[2 * np][1],
                                        bh[2 * np + 1][0], bh[2 * np + 1][1]);
            }
            uint32_t ah[2][4];
#pragma unroll
            for (int mt = 0; mt < 2; mt++) {
                int r = wm * 32 + mt * 16 + (lane & 15);
                int c8 = kk * 2 + (lane >> 4);
                ldsm4(sA + swz(r, c8), ah[mt][0], ah[mt][1], ah[mt][2], ah[mt][3]);
            }
#pragma unroll
            for (int mt = 0; mt < 2; mt++)
#pragma unroll
                for (int nt = 0; nt < 8; nt++)
                    mma16816(acc[mt][nt], ah[mt], bh[nt]);
        }
    }

    const int row0 = bM * 128 + wm * 32;
    const int col0 = bN * 128 + wn * 64;
    const int tr = lane >> 2, tc = (lane & 3) << 1;
    if (EPI == 0) {
        f16* C0 = reinterpret_cast<f16*>(Co);
#pragma unroll
        for (int mt = 0; mt < 2; mt++)
#pragma unroll
            for (int nt = 0; nt < 8; nt++) {
                int p = row0 + mt * 16 + tr, x = col0 + nt * 8 + tc;
                __half2 a01 = __floats2half2_rn(acc[mt][nt][0], acc[mt][nt][1]);
                __half2 a23 = __floats2half2_rn(acc[mt][nt][2], acc[mt][nt][3]);
                *reinterpret_cast<uint32_t*>(C0 + (size_t)p * N + x) =
                    *reinterpret_cast<uint32_t*>(&a01);
                *reinterpret_cast<uint32_t*>(C0 + (size_t)(p + 8) * N + x) =
                    *reinterpret_cast<uint32_t*>(&a23);
            }
    } else {
        float* C0 = reinterpret_cast<float*>(Co);
        const float* R0 = Res;
#pragma unroll
        for (int mt = 0; mt < 2; mt++)
#pragma unroll
            for (int nt = 0; nt < 8; nt++) {
                int p = row0 + mt * 16 + tr, x = col0 + nt * 8 + tc;
                float2 r0 = *reinterpret_cast<const float2*>(R0 + (size_t)p * N + x);
                float2 r1 = *reinterpret_cast<const float2*>(R0 + (size_t)(p + 8) * N + x);
                *reinterpret_cast<float2*>(C0 + (size_t)p * N + x) =
                    make_float2(acc[mt][nt][0] + r0.x, acc[mt][nt][1] + r0.y);
                *reinterpret_cast<float2*>(C0 + (size_t)(p + 8) * N + x) =
                    make_float2(acc[mt][nt][2] + r1.x, acc[mt][nt][3] + r1.y);
            }
    }
}

// ---------------- softmax (exp-domain) + near-threshold exact repair ----------------
DI float blockMax(float v, float* red) {
#pragma unroll
    for (int o = 16; o; o >>= 1) v = fmaxf(v, __shfl_xor_sync(0xffffffffu, v, o));
    __syncthreads();
    if ((threadIdx.x & 31) == 0) red[threadIdx.x >> 5] = v;
    __syncthreads();
    float r = red[0];
#pragma unroll
    for (int i = 1; i < 8; i++) r = fmaxf(r, red[i]);
    return r;
}
DI float blockSum(float v, float* red) {
#pragma unroll
    for (int o = 16; o; o >>= 1) v += __shfl_xor_sync(0xffffffffu, v, o);
    __syncthreads();
    if ((threadIdx.x & 31) == 0) red[threadIdx.x >> 5] = v;
    __syncthreads();
    float r = 0.f;
#pragma unroll
    for (int i = 0; i < 8; i++) r += red[i];
    return r;
}

constexpr int FCAP = 1024;

// S/W/qh/ql/kh/kl are BASE pointers; all addressing uses the global row.
__global__ void __launch_bounds__(256) softmax_kernel(
    const f16* __restrict__ S,
    const f16* __restrict__ qh, const f16* __restrict__ ql,
    const f16* __restrict__ kh, const f16* __restrict__ kl,
    f16* __restrict__ W, int row_base)
{
    __shared__ float red[8];
    __shared__ float q_s[1024];
    __shared__ int   nf;
    __shared__ int   fx[FCAP];
    __shared__ float fsn[FCAP];

    const int row = row_base + blockIdx.x;     // global row: b*Pn + p
    const int bz  = row >> 10;                 // Pn = 1024
    const int t = threadIdx.x;
    const int lane = t & 31, warp = t >> 5;

    // preload exact q row (qh+ql) to smem
    {
        const uint2 ph = reinterpret_cast<const uint2*>(qh + (size_t)row * 1024)[t];
        const uint2 pl = reinterpret_cast<const uint2*>(ql + (size_t)row * 1024)[t];
        __half2 h0 = *reinterpret_cast<const __half2*>(&ph.x);
        __half2 h1 = *reinterpret_cast<const __half2*>(&ph.y);
        __half2 l0 = *reinterpret_cast<const __half2*>(&pl.x);
        __half2 l1 = *reinterpret_cast<const __half2*>(&pl.y);
        q_s[4 * t + 0] = __low2float(h0)  + __low2float(l0);
        q_s[4 * t + 1] = __high2float(h0) + __high2float(l0);
        q_s[4 * t + 2] = __low2float(h1)  + __low2float(l1);
        q_s[4 * t + 3] = __high2float(h1) + __high2float(l1);
    }
    if (t == 0) nf = 0;

    // load f16 scores: 8 x uint2 = 32 values per thread
    const uint2* s2 = reinterpret_cast<const uint2*>(S + (size_t)row * Xn);
    float v[8][4];
    float m = -1e30f;
#pragma unroll
    for (int i = 0; i < 8; i++) {
        uint2 pk = s2[t + i * 256];
        __half2 a = *reinterpret_cast<const __half2*>(&pk.x);
        __half2 b = *reinterpret_cast<const __half2*>(&pk.y);
        v[i][0] = __low2float(a);  v[i][1] = __high2float(a);
        v[i][2] = __low2float(b);  v[i][3] = __high2float(b);
        m = fmaxf(m, fmaxf(fmaxf(v[i][0], v[i][1]), fmaxf(v[i][2], v[i][3])));
    }
    m = blockMax(m, red);                      // also fences q_s / nf writes

    // single exp pass: v becomes e = exp(s - m)
    float z = 0.f;
#pragma unroll
    for (int i = 0; i < 8; i++)
#pragma unroll
        for (int j = 0; j < 4; j++) { v[i][j] = __expf(v[i][j] - m); z += v[i][j]; }
    z = blockSum(z, red);

    // flag entries within +-4e-3 (log domain) of the approximate threshold
    const float ethr1 = 0.0005f * z;
    const float lo = ethr1 * 0.99601f;         // exp(-4e-3)
    const float hi = ethr1 * 1.00401f;         // exp(+4e-3)
#pragma unroll
    for (int i = 0; i < 8; i++)
#pragma unroll
        for (int j = 0; j < 4; j++) {
            if (v[i][j] > lo && v[i][j] < hi) {
                int sl = atomicAdd(&nf, 1);
                if (sl < FCAP) fx[sl] = 4 * (t + i * 256) + j;
            }
        }
    __syncthreads();
    const int nfc = min(nf, FCAP);

    // exact fp32 recompute of flagged scores: one warp per entry
    for (int e = warp; e < nfc; e += 8) {
        const int x = fx[e];
        const uint2* khp = reinterpret_cast<const uint2*>(kh + ((size_t)bz * Xn + x) * 1024);
        const uint2* klp = reinterpret_cast<const uint2*>(kl + ((size_t)bz * Xn + x) * 1024);
        float sum = 0.f;
#pragma unroll
        for (int jj = 0; jj < 8; jj++) {
            const int c4 = lane + jj * 32;
            const uint2 ph = khp[c4];
            const uint2 pl = klp[c4];
            __half2 h0 = *reinterpret_cast<const __half2*>(&ph.x);
            __half2 h1 = *reinterpret_cast<const __half2*>(&ph.y);
            __half2 l0 = *reinterpret_cast<const __half2*>(&pl.x);
            __half2 l1 = *reinterpret_cast<const __half2*>(&pl.y);
            sum = fmaf(q_s[4 * c4 + 0], __low2float(h0)  + __low2float(l0),  sum);
            sum = fmaf(q_s[4 * c4 + 1], __high2float(h0) + __high2float(l0), sum);
            sum = fmaf(q_s[4 * c4 + 2], __low2float(h1)  + __low2float(l1),  sum);
            sum = fmaf(q_s[4 * c4 + 3], __high2float(h1) + __high2float(l1), sum);
        }
#pragma unroll
        for (int o = 16; o; o >>= 1) sum += __shfl_xor_sync(0xffffffffu, sum, o);
        if (lane == 0) fsn[e] = __expf(sum - m);   // exact exp value
    }
    __syncthreads();

    // patch my registers with exact exp values
    for (int e = 0; e < nfc; e++) {
        const int x = fx[e];
        const int q4 = x >> 2;
        if ((q4 & 255) == t) v[q4 >> 8][x & 3] = fsn[e];
    }

    // rebuild Z and threshold from patched values (deterministic full reduction)
    float z_p = 0.f;
#pragma unroll
    for (int i = 0; i < 8; i++)
#pragma unroll
        for (int j = 0; j < 4; j++) z_p += v[i][j];
    z_p = blockSum(z_p, red);
    const float ethr = 0.0005f * z_p;

    float z2 = 0.f;
#pragma unroll
    for (int i = 0; i < 8; i++)
#pragma unroll
        for (int j = 0; j < 4; j++)
            if (v[i][j] >= ethr) z2 += v[i][j];
    z2 = blockSum(z2, red);
    const float inv = 1.f / z2;

    uint2* wo = reinterpret_cast<uint2*>(W + (size_t)row * Xn);
#pragma unroll
    for (int i = 0; i < 8; i++) {
        float w0 = (v[i][0] >= ethr) ? v[i][0] * inv : 0.f;
        float w1 = (v[i][1] >= ethr) ? v[i][1] * inv : 0.f;
        float w2 = (v[i][2] >= ethr) ? v[i][2] * inv : 0.f;
        float w3 = (v[i][3] >= ethr) ? v[i][3] * inv : 0.f;
        __half2 h01 = __floats2half2_rn(w0, w1);
        __half2 h23 = __floats2half2_rn(w2, w3);
        uint2 pk;
        pk.x = *reinterpret_cast<uint32_t*>(&h01);
        pk.y = *reinterpret_cast<uint32_t*>(&h23);
        wo[t + i * 256] = pk;
    }
}

// ---------------- launch: batch-pipelined GEMM1 -> softmax -> GEMM2 ----------------
extern "C" void kernel_launch(void* const* d_in, const int* in_sizes, int n_in,
                              void* d_out, int out_size)
{
    const float* feat  = (const float*)d_in[0];
    const float* mem_k = (const float*)d_in[1];
    const float* mem_v = (const float*)d_in[2];
    const float* mem_c = (const float*)d_in[3];
    // d_in[4] = mem_attn (unused by reference)
    const float* gq = (const float*)d_in[5];
    const float* bq = (const float*)d_in[6];
    const float* gk = (const float*)d_in[7];
    const float* bk = (const float*)d_in[8];
    const float* gv = (const float*)d_in[9];
    const float* bv = (const float*)d_in[10];
    float* out = (float*)d_out;

    f16 *qh, *ql, *kh, *kl, *v, *vt, *S, *W;
    cudaGetSymbolAddress((void**)&qh, g_qh);
    cudaGetSymbolAddress((void**)&ql, g_ql);
    cudaGetSymbolAddress((void**)&kh, g_kh);
    cudaGetSymbolAddress((void**)&kl, g_kl);
    cudaGetSymbolAddress((void**)&v,  g_v);
    cudaGetSymbolAddress((void**)&vt, g_vt);
    cudaGetSymbolAddress((void**)&S,  g_S);
    cudaGetSymbolAddress((void**)&W,  g_W);

    // side stream + events, created once on the first (non-capturing) call
    static cudaStream_t s2 = nullptr;
    static cudaEvent_t evFork = nullptr, evJoin = nullptr;
    static cudaEvent_t evG1[Bn] = {nullptr, nullptr, nullptr, nullptr};
    if (!s2) {
        cudaStreamCreateWithFlags(&s2, cudaStreamNonBlocking);
        cudaEventCreateWithFlags(&evFork, cudaEventDisableTiming);
        cudaEventCreateWithFlags(&evJoin, cudaEventDisableTiming);
        for (int b = 0; b < Bn; b++)
            cudaEventCreateWithFlags(&evG1[b], cudaEventDisableTiming);
    }

    // smem: 3 stages x 32KB = 98304 -> 2 CTAs/SM
    const int SM = 3 * 2 * 16384;
    cudaFuncSetAttribute(gemm_kernel<3, 0>, cudaFuncAttributeMaxDynamicSharedMemorySize, SM);
    cudaFuncSetAttribute(gemm_kernel<3, 1>, cudaFuncAttributeMaxDynamicSharedMemorySize, SM);

    // fork: V-path (ln_v + transpose) runs on the side stream
    cudaEventRecord(evFork, 0);
    cudaStreamWaitEvent(s2, evFork, 0);
    ln_kernel<<<Bn * Xn, 256, 0, s2>>>(mem_v, v, nullptr, gv, bv, nullptr, 1.f);
    transpose_kernel<<<dim3(Xn / 32, Cn / 32, Bn), dim3(32, 8), 0, s2>>>(v, vt);

    // main path: LN for q and k
    ln_kernel<<<Bn * Pn, 256>>>(feat,  qh, ql, gq, bq, nullptr, S32);
    ln_kernel<<<Bn * Xn, 256>>>(mem_k, kh, kl, gk, bk, mem_c,   S32);

    // per-batch GEMM1 on main stream, with completion events
    for (int b = 0; b < Bn; b++) {
        gemm_kernel<3, 0><<<dim3(Xn / 128, Pn / 128, 1), 256, SM>>>(
            qh + (size_t)b * Pn * Cn, kh + (size_t)b * Xn * Cn,
            S + (size_t)b * Pn * Xn, nullptr, Pn, Xn, Cn);
        cudaEventRecord(evG1[b], 0);
    }

    // per-batch softmax + GEMM2 on the side stream, pipelined under later GEMM1s
    for (int b = 0; b < Bn; b++) {
        cudaStreamWaitEvent(s2, evG1[b], 0);
        // NOTE: S and W are passed as BASE pointers; softmax indexes by global row.
        softmax_kernel<<<Pn, 256, 0, s2>>>(
            S, qh, ql, kh, kl, W, b * Pn);
        gemm_kernel<3, 1><<<dim3(Cn / 128, Pn / 128, 1), 256, SM, s2>>>(
            W + (size_t)b * Pn * Xn, vt + (size_t)b * Cn * Xn,
            out + (size_t)b * Pn * Cn, feat + (size_t)b * Pn * Cn, Pn, Cn, Xn);
    }
    cudaEventRecord(evJoin, s2);
    cudaStreamWaitEvent(0, evJoin, 0);
}

// round 12
// speedup vs baseline: 1.4793x; 1.4793x over previous
#include <cuda_runtime.h>
#include <cuda_fp16.h>
#include <cstdint>
#include <cstddef>

typedef __half f16;
#define DI __device__ __forceinline__

constexpr int Bn = 4, Pn = 1024, Xn = 8192, Cn = 1024;
// symmetric fold: q *= S32, k *= c * S32  ->  q.k carries 1/32 = 1/sqrt(C)
#define S32 0.1767766952966369f

// ---------------- scratch (device globals, no allocation) ----------------
__device__ f16   g_qh[(size_t)Bn * Pn * Cn];
__device__ f16   g_ql[(size_t)Bn * Pn * Cn];   // only read by softmax repair
__device__ f16   g_kh[(size_t)Bn * Xn * Cn];
__device__ f16   g_kl[(size_t)Bn * Xn * Cn];   // only read by softmax repair
__device__ f16   g_v [(size_t)Bn * Xn * Cn];
__device__ f16   g_vt[(size_t)Bn * Cn * Xn];
__device__ f16   g_S [(size_t)Bn * Pn * Xn];   // scores f16 (repaired later)
__device__ f16   g_W [(size_t)Bn * Pn * Xn];

// ---------------- PTX helpers ----------------
DI void cp_async16(uint32_t saddr, const void* gptr) {
    asm volatile("cp.async.cg.shared.global [%0], [%1], 16;\n" :: "r"(saddr), "l"(gptr));
}
DI void cp_commit() { asm volatile("cp.async.commit_group;\n"); }
template <int N> DI void cp_wait() { asm volatile("cp.async.wait_group %0;\n" :: "n"(N)); }

DI void ldsm4(uint32_t addr, uint32_t& r0, uint32_t& r1, uint32_t& r2, uint32_t& r3) {
    asm volatile("ldmatrix.sync.aligned.m8n8.x4.shared.b16 {%0,%1,%2,%3}, [%4];\n"
                 : "=r"(r0), "=r"(r1), "=r"(r2), "=r"(r3) : "r"(addr));
}
DI void mma16816(float c[4], const uint32_t a[4], const uint32_t b[2]) {
    asm volatile(
        "mma.sync.aligned.m16n8k16.row.col.f32.f16.f16.f32 "
        "{%0,%1,%2,%3}, {%4,%5,%6,%7}, {%8,%9}, {%0,%1,%2,%3};\n"
        : "+f"(c[0]), "+f"(c[1]), "+f"(c[2]), "+f"(c[3])
        : "r"(a[0]), "r"(a[1]), "r"(a[2]), "r"(a[3]), "r"(b[0]), "r"(b[1]));
}

// Swizzled byte offset inside a 128-row x 64-col f16 tile (128B rows, SW128 XOR).
DI uint32_t swz(int r, int c8) { return (uint32_t)(r * 128 + ((c8 ^ (r & 7)) << 4)); }

// ---------------- LayerNorm -> f16 (optionally hi/lo split), C = 1024 ----------------
__global__ void __launch_bounds__(256) ln_kernel(
    const float* __restrict__ src, f16* __restrict__ dst_h, f16* __restrict__ dst_l,
    const float* __restrict__ gamma, const float* __restrict__ beta,
    const float* __restrict__ cscale, float sconst)
{
    const int row = blockIdx.x;
    const int t = threadIdx.x;
    const float4* s4 = reinterpret_cast<const float4*>(src) + (size_t)row * 256;
    float4 x = s4[t];
    float sum = x.x + x.y + x.z + x.w;
    float sq  = fmaf(x.x, x.x, fmaf(x.y, x.y, fmaf(x.z, x.z, x.w * x.w)));
#pragma unroll
    for (int o = 16; o; o >>= 1) {
        sum += __shfl_xor_sync(0xffffffffu, sum, o);
        sq  += __shfl_xor_sync(0xffffffffu, sq,  o);
    }
    __shared__ float s_sum[8], s_sq[8];
    if ((t & 31) == 0) { s_sum[t >> 5] = sum; s_sq[t >> 5] = sq; }
    __syncthreads();
    sum = 0.f; sq = 0.f;
#pragma unroll
    for (int i = 0; i < 8; i++) { sum += s_sum[i]; sq += s_sq[i]; }
    const float mu  = sum * (1.f / 1024.f);
    const float var = sq * (1.f / 1024.f) - mu * mu;
    const float rs  = rsqrtf(var + 1e-5f);
    const float sc  = (cscale ? __ldg(cscale + row) : 1.f) * sconst;

    const float4 g = reinterpret_cast<const float4*>(gamma)[t];
    const float4 b = reinterpret_cast<const float4*>(beta)[t];
    float y[4];
    y[0] = ((x.x - mu) * rs * g.x + b.x) * sc;
    y[1] = ((x.y - mu) * rs * g.y + b.y) * sc;
    y[2] = ((x.z - mu) * rs * g.z + b.z) * sc;
    y[3] = ((x.w - mu) * rs * g.w + b.w) * sc;

    __half2 h01 = __floats2half2_rn(y[0], y[1]);
    __half2 h23 = __floats2half2_rn(y[2], y[3]);
    uint2 pk;
    pk.x = *reinterpret_cast<uint32_t*>(&h01);
    pk.y = *reinterpret_cast<uint32_t*>(&h23);
    reinterpret_cast<uint2*>(dst_h + (size_t)row * 1024)[t] = pk;

    if (dst_l) {
        float l0 = y[0] - __half2float(__low2half(h01));
        float l1 = y[1] - __half2float(__high2half(h01));
        float l2 = y[2] - __half2float(__low2half(h23));
        float l3 = y[3] - __half2float(__high2half(h23));
        __half2 l01 = __floats2half2_rn(l0, l1);
        __half2 l23 = __floats2half2_rn(l2, l3);
        uint2 pl;
        pl.x = *reinterpret_cast<uint32_t*>(&l01);
        pl.y = *reinterpret_cast<uint32_t*>(&l23);
        reinterpret_cast<uint2*>(dst_l + (size_t)row * 1024)[t] = pl;
    }
}

// ---------------- f16 transpose: [b][X][C] -> [b][C][X] ----------------
__global__ void transpose_kernel(const f16* __restrict__ src, f16* __restrict__ dst)
{
    __shared__ f16 tile[32][34];
    const int b = blockIdx.z;
    const int x0 = blockIdx.x << 5, c0 = blockIdx.y << 5;
    const f16* s = src + ((size_t)b * Xn + x0) * Cn + c0;
#pragma unroll
    for (int j = 0; j < 4; j++)
        tile[threadIdx.y + j * 8][threadIdx.x] =
            s[(size_t)(threadIdx.y + j * 8) * Cn + threadIdx.x];
    __syncthreads();
    f16* d = dst + ((size_t)b * Cn + c0) * Xn + x0;
#pragma unroll
    for (int j = 0; j < 4; j++)
        d[(size_t)(threadIdx.y + j * 8) * Xn + threadIdx.x] =
            tile[threadIdx.x][threadIdx.y + j * 8];
}

// ---------------- tiled f16 GEMM: 128x128 CTA tile, K-tiles of 64 ----------------
// Batched over blockIdx.z. EPI 0: store f16 scores.  EPI 1: store fp32 (acc + Res).
template <int STAGES, int EPI>
__global__ void __launch_bounds__(256, 2) gemm_kernel(
    const f16* __restrict__ A0, const f16* __restrict__ B0,
    void* __restrict__ Co, const float* __restrict__ Res,
    int M, int N, int K)
{
    extern __shared__ __align__(1024) char smem_raw[];
    constexpr int TILE = 16384;                       // 128x64 f16
    constexpr int SS   = 2 * TILE;
    const int tid = threadIdx.x, lane = tid & 31, warp = tid >> 5;
    const int wm = warp & 3, wn = warp >> 2;          // 4 x 2 warp grid
    const int bN = blockIdx.x, bM = blockIdx.y, bz = blockIdx.z;

    const f16* Ap = A0 + (size_t)bz * M * K + (size_t)bM * 128 * K;
    const f16* Bp = B0 + (size_t)bz * N * K + (size_t)bN * 128 * K;

    const uint32_t sb = (uint32_t)__cvta_generic_to_shared(smem_raw);
    const int KT = K >> 6;

    auto fill = [&](int t) {
        const int k0 = t * 64;
        const uint32_t base = sb + (uint32_t)(t % STAGES) * SS;
#pragma unroll
        for (int i = 0; i < 4; i++) {
            int idx = tid + i * 256; int r = idx >> 3, c8 = idx & 7;
            cp_async16(base + swz(r, c8), Ap + (size_t)r * K + k0 + c8 * 8);
        }
#pragma unroll
        for (int i = 0; i < 4; i++) {
            int idx = tid + i * 256; int r = idx >> 3, c8 = idx & 7;
            cp_async16(base + TILE + swz(r, c8), Bp + (size_t)r * K + k0 + c8 * 8);
        }
        cp_commit();
    };

    float acc[2][8][4];
#pragma unroll
    for (int mt = 0; mt < 2; mt++)
#pragma unroll
        for (int nt = 0; nt < 8; nt++)
#pragma unroll
            for (int i = 0; i < 4; i++) acc[mt][nt][i] = 0.f;

#pragma unroll
    for (int t = 0; t < STAGES - 1; t++) fill(t);

    for (int kt = 0; kt < KT; kt++) {
        cp_wait<STAGES - 2>();
        __syncthreads();
        { const int t = kt + STAGES - 1; if (t < KT) fill(t); else cp_commit(); }

        const uint32_t base = sb + (uint32_t)(kt % STAGES) * SS;
        const uint32_t sA = base;
        const uint32_t sB = base + TILE;
#pragma unroll
        for (int kk = 0; kk < 4; kk++) {
            uint32_t bh[8][2];
#pragma unroll
            for (int np = 0; np < 4; np++) {
                int r = wn * 64 + np * 16 + ((lane >> 4) << 3) + (lane & 7);
                int c8 = kk * 2 + ((lane >> 3) & 1);
                ldsm4(sB + swz(r, c8), bh[2 * np][0], bh[2 * np][1],
                                        bh[2 * np + 1][0], bh[2 * np + 1][1]);
            }
            uint32_t ah[2][4];
#pragma unroll
            for (int mt = 0; mt < 2; mt++) {
                int r = wm * 32 + mt * 16 + (lane & 15);
                int c8 = kk * 2 + (lane >> 4);
                ldsm4(sA + swz(r, c8), ah[mt][0], ah[mt][1], ah[mt][2], ah[mt][3]);
            }
#pragma unroll
            for (int mt = 0; mt < 2; mt++)
#pragma unroll
                for (int nt = 0; nt < 8; nt++)
                    mma16816(acc[mt][nt], ah[mt], bh[nt]);
        }
    }

    const int row0 = bM * 128 + wm * 32;
    const int col0 = bN * 128 + wn * 64;
    const int tr = lane >> 2, tc = (lane & 3) << 1;
    if (EPI == 0) {
        f16* C0 = reinterpret_cast<f16*>(Co) + (size_t)bz * M * N;
#pragma unroll
        for (int mt = 0; mt < 2; mt++)
#pragma unroll
            for (int nt = 0; nt < 8; nt++) {
                int p = row0 + mt * 16 + tr, x = col0 + nt * 8 + tc;
                __half2 a01 = __floats2half2_rn(acc[mt][nt][0], acc[mt][nt][1]);
                __half2 a23 = __floats2half2_rn(acc[mt][nt][2], acc[mt][nt][3]);
                *reinterpret_cast<uint32_t*>(C0 + (size_t)p * N + x) =
                    *reinterpret_cast<uint32_t*>(&a01);
                *reinterpret_cast<uint32_t*>(C0 + (size_t)(p + 8) * N + x) =
                    *reinterpret_cast<uint32_t*>(&a23);
            }
    } else {
        float* C0 = reinterpret_cast<float*>(Co) + (size_t)bz * M * N;
        const float* R0 = Res + (size_t)bz * M * N;
#pragma unroll
        for (int mt = 0; mt < 2; mt++)
#pragma unroll
            for (int nt = 0; nt < 8; nt++) {
                int p = row0 + mt * 16 + tr, x = col0 + nt * 8 + tc;
                float2 r0 = *reinterpret_cast<const float2*>(R0 + (size_t)p * N + x);
                float2 r1 = *reinterpret_cast<const float2*>(R0 + (size_t)(p + 8) * N + x);
                *reinterpret_cast<float2*>(C0 + (size_t)p * N + x) =
                    make_float2(acc[mt][nt][0] + r0.x, acc[mt][nt][1] + r0.y);
                *reinterpret_cast<float2*>(C0 + (size_t)(p + 8) * N + x) =
                    make_float2(acc[mt][nt][2] + r1.x, acc[mt][nt][3] + r1.y);
            }
    }
}

// ---------------- softmax (exp-domain) + near-threshold exact repair ----------------
DI float blockMax(float v, float* red) {
#pragma unroll
    for (int o = 16; o; o >>= 1) v = fmaxf(v, __shfl_xor_sync(0xffffffffu, v, o));
    __syncthreads();
    if ((threadIdx.x & 31) == 0) red[threadIdx.x >> 5] = v;
    __syncthreads();
    float r = red[0];
#pragma unroll
    for (int i = 1; i < 8; i++) r = fmaxf(r, red[i]);
    return r;
}
DI float blockSum(float v, float* red) {
#pragma unroll
    for (int o = 16; o; o >>= 1) v += __shfl_xor_sync(0xffffffffu, v, o);
    __syncthreads();
    if ((threadIdx.x & 31) == 0) red[threadIdx.x >> 5] = v;
    __syncthreads();
    float r = 0.f;
#pragma unroll
    for (int i = 0; i < 8; i++) r += red[i];
    return r;
}

constexpr int FCAP = 1024;

// S/W/qh/ql/kh/kl are BASE pointers; all addressing uses the global row.
__global__ void __launch_bounds__(256) softmax_kernel(
    const f16* __restrict__ S,
    const f16* __restrict__ qh, const f16* __restrict__ ql,
    const f16* __restrict__ kh, const f16* __restrict__ kl,
    f16* __restrict__ W)
{
    __shared__ float red[8];
    __shared__ float q_s[1024];
    __shared__ int   nf;
    __shared__ int   fx[FCAP];
    __shared__ float fsn[FCAP];

    const int row = blockIdx.x;                // global row: b*Pn + p
    const int bz  = row >> 10;                 // Pn = 1024
    const int t = threadIdx.x;
    const int lane = t & 31, warp = t >> 5;

    // preload exact q row (qh+ql) to smem
    {
        const uint2 ph = reinterpret_cast<const uint2*>(qh + (size_t)row * 1024)[t];
        const uint2 pl = reinterpret_cast<const uint2*>(ql + (size_t)row * 1024)[t];
        __half2 h0 = *reinterpret_cast<const __half2*>(&ph.x);
        __half2 h1 = *reinterpret_cast<const __half2*>(&ph.y);
        __half2 l0 = *reinterpret_cast<const __half2*>(&pl.x);
        __half2 l1 = *reinterpret_cast<const __half2*>(&pl.y);
        q_s[4 * t + 0] = __low2float(h0)  + __low2float(l0);
        q_s[4 * t + 1] = __high2float(h0) + __high2float(l0);
        q_s[4 * t + 2] = __low2float(h1)  + __low2float(l1);
        q_s[4 * t + 3] = __high2float(h1) + __high2float(l1);
    }
    if (t == 0) nf = 0;

    // load f16 scores: 8 x uint2 = 32 values per thread
    const uint2* s2 = reinterpret_cast<const uint2*>(S + (size_t)row * Xn);
    float v[8][4];
    float m = -1e30f;
#pragma unroll
    for (int i = 0; i < 8; i++) {
        uint2 pk = s2[t + i * 256];
        __half2 a = *reinterpret_cast<const __half2*>(&pk.x);
        __half2 b = *reinterpret_cast<const __half2*>(&pk.y);
        v[i][0] = __low2float(a);  v[i][1] = __high2float(a);
        v[i][2] = __low2float(b);  v[i][3] = __high2float(b);
        m = fmaxf(m, fmaxf(fmaxf(v[i][0], v[i][1]), fmaxf(v[i][2], v[i][3])));
    }
    m = blockMax(m, red);                      // also fences q_s / nf writes

    // single exp pass: v becomes e = exp(s - m)
    float z = 0.f;
#pragma unroll
    for (int i = 0; i < 8; i++)
#pragma unroll
        for (int j = 0; j < 4; j++) { v[i][j] = __expf(v[i][j] - m); z += v[i][j]; }
    z = blockSum(z, red);

    // flag entries within +-4e-3 (log domain) of the approximate threshold
    const float ethr1 = 0.0005f * z;
    const float lo = ethr1 * 0.99601f;         // exp(-4e-3)
    const float hi = ethr1 * 1.00401f;         // exp(+4e-3)
#pragma unroll
    for (int i = 0; i < 8; i++)
#pragma unroll
        for (int j = 0; j < 4; j++) {
            if (v[i][j] > lo && v[i][j] < hi) {
                int sl = atomicAdd(&nf, 1);
                if (sl < FCAP) fx[sl] = 4 * (t + i * 256) + j;
            }
        }
    __syncthreads();
    const int nfc = min(nf, FCAP);

    // exact fp32 recompute of flagged scores: one warp per entry
    for (int e = warp; e < nfc; e += 8) {
        const int x = fx[e];
        const uint2* khp = reinterpret_cast<const uint2*>(kh + ((size_t)bz * Xn + x) * 1024);
        const uint2* klp = reinterpret_cast<const uint2*>(kl + ((size_t)bz * Xn + x) * 1024);
        float sum = 0.f;
#pragma unroll
        for (int jj = 0; jj < 8; jj++) {
            const int c4 = lane + jj * 32;
            const uint2 ph = khp[c4];
            const uint2 pl = klp[c4];
            __half2 h0 = *reinterpret_cast<const __half2*>(&ph.x);
            __half2 h1 = *reinterpret_cast<const __half2*>(&ph.y);
            __half2 l0 = *reinterpret_cast<const __half2*>(&pl.x);
            __half2 l1 = *reinterpret_cast<const __half2*>(&pl.y);
            sum = fmaf(q_s[4 * c4 + 0], __low2float(h0)  + __low2float(l0),  sum);
            sum = fmaf(q_s[4 * c4 + 1], __high2float(h0) + __high2float(l0), sum);
            sum = fmaf(q_s[4 * c4 + 2], __low2float(h1)  + __low2float(l1),  sum);
            sum = fmaf(q_s[4 * c4 + 3], __high2float(h1) + __high2float(l1), sum);
        }
#pragma unroll
        for (int o = 16; o; o >>= 1) sum += __shfl_xor_sync(0xffffffffu, sum, o);
        if (lane == 0) fsn[e] = __expf(sum - m);   // exact exp value
    }
    __syncthreads();

    // patch my registers with exact exp values
    for (int e = 0; e < nfc; e++) {
        const int x = fx[e];
        const int q4 = x >> 2;
        if ((q4 & 255) == t) v[q4 >> 8][x & 3] = fsn[e];
    }

    // rebuild Z and threshold from patched values (deterministic full reduction)
    float z_p = 0.f;
#pragma unroll
    for (int i = 0; i < 8; i++)
#pragma unroll
        for (int j = 0; j < 4; j++) z_p += v[i][j];
    z_p = blockSum(z_p, red);
    const float ethr = 0.0005f * z_p;

    float z2 = 0.f;
#pragma unroll
    for (int i = 0; i < 8; i++)
#pragma unroll
        for (int j = 0; j < 4; j++)
            if (v[i][j] >= ethr) z2 += v[i][j];
    z2 = blockSum(z2, red);
    const float inv = 1.f / z2;

    uint2* wo = reinterpret_cast<uint2*>(W + (size_t)row * Xn);
#pragma unroll
    for (int i = 0; i < 8; i++) {
        float w0 = (v[i][0] >= ethr) ? v[i][0] * inv : 0.f;
        float w1 = (v[i][1] >= ethr) ? v[i][1] * inv : 0.f;
        float w2 = (v[i][2] >= ethr) ? v[i][2] * inv : 0.f;
        float w3 = (v[i][3] >= ethr) ? v[i][3] * inv : 0.f;
        __half2 h01 = __floats2half2_rn(w0, w1);
        __half2 h23 = __floats2half2_rn(w2, w3);
        uint2 pk;
        pk.x = *reinterpret_cast<uint32_t*>(&h01);
        pk.y = *reinterpret_cast<uint32_t*>(&h23);
        wo[t + i * 256] = pk;
    }
}

// ---------------- launch (R8 topology: V-path fork only, monolithic GEMMs) ----------
extern "C" void kernel_launch(void* const* d_in, const int* in_sizes, int n_in,
                              void* d_out, int out_size)
{
    const float* feat  = (const float*)d_in[0];
    const float* mem_k = (const float*)d_in[1];
    const float* mem_v = (const float*)d_in[2];
    const float* mem_c = (const float*)d_in[3];
    // d_in[4] = mem_attn (unused by reference)
    const float* gq = (const float*)d_in[5];
    const float* bq = (const float*)d_in[6];
    const float* gk = (const float*)d_in[7];
    const float* bk = (const float*)d_in[8];
    const float* gv = (const float*)d_in[9];
    const float* bv = (const float*)d_in[10];
    float* out = (float*)d_out;

    f16 *qh, *ql, *kh, *kl, *v, *vt, *S, *W;
    cudaGetSymbolAddress((void**)&qh, g_qh);
    cudaGetSymbolAddress((void**)&ql, g_ql);
    cudaGetSymbolAddress((void**)&kh, g_kh);
    cudaGetSymbolAddress((void**)&kl, g_kl);
    cudaGetSymbolAddress((void**)&v,  g_v);
    cudaGetSymbolAddress((void**)&vt, g_vt);
    cudaGetSymbolAddress((void**)&S,  g_S);
    cudaGetSymbolAddress((void**)&W,  g_W);

    // side stream + events, created once on the first (non-capturing) call
    static cudaStream_t s2 = nullptr;
    static cudaEvent_t evFork = nullptr, evJoin = nullptr;
    if (!s2) {
        cudaStreamCreateWithFlags(&s2, cudaStreamNonBlocking);
        cudaEventCreateWithFlags(&evFork, cudaEventDisableTiming);
        cudaEventCreateWithFlags(&evJoin, cudaEventDisableTiming);
    }

    // smem: 3 stages x 32KB = 98304 -> 2 CTAs/SM
    const int SM = 3 * 2 * 16384;
    cudaFuncSetAttribute(gemm_kernel<3, 0>, cudaFuncAttributeMaxDynamicSharedMemorySize, SM);
    cudaFuncSetAttribute(gemm_kernel<3, 1>, cudaFuncAttributeMaxDynamicSharedMemorySize, SM);

    // fork: V-path (ln_v + transpose) runs on the side stream
    cudaEventRecord(evFork, 0);
    cudaStreamWaitEvent(s2, evFork, 0);
    ln_kernel<<<Bn * Xn, 256, 0, s2>>>(mem_v, v, nullptr, gv, bv, nullptr, 1.f);
    transpose_kernel<<<dim3(Xn / 32, Cn / 32, Bn), dim3(32, 8), 0, s2>>>(v, vt);
    cudaEventRecord(evJoin, s2);

    // main path: LN for q and k
    ln_kernel<<<Bn * Pn, 256>>>(feat,  qh, ql, gq, bq, nullptr, S32);
    ln_kernel<<<Bn * Xn, 256>>>(mem_k, kh, kl, gk, bk, mem_c,   S32);

    // S~ = qh @ kh^T  (single fp16 pass, f16 scores; repaired in softmax)
    gemm_kernel<3, 0><<<dim3(Xn / 128, Pn / 128, Bn), 256, SM>>>(
        qh, kh, S, nullptr, Pn, Xn, Cn);

    softmax_kernel<<<Bn * Pn, 256>>>(S, qh, ql, kh, kl, W);

    // join: GEMM2 needs vt from the side stream
    cudaStreamWaitEvent(0, evJoin, 0);

    // out = W @ v^T + feat
    gemm_kernel<3, 1><<<dim3(Cn / 128, Pn / 128, Bn), 256, SM>>>(
        W, vt, out, feat, Pn, Cn, Xn);
}

// round 13
// speedup vs baseline: 1.4809x; 1.0011x over previous
#include <cuda_runtime.h>
#include <cuda_fp16.h>
#include <cstdint>
#include <cstddef>

typedef __half f16;
#define DI __device__ __forceinline__

constexpr int Bn = 4, Pn = 1024, Xn = 8192, Cn = 1024;
// symmetric fold: q *= S32, k *= c * S32  ->  q.k carries 1/32 = 1/sqrt(C)
#define S32 0.1767766952966369f

// ---------------- scratch (device globals, no allocation) ----------------
__device__ f16   g_qh[(size_t)Bn * Pn * Cn];
__device__ f16   g_ql[(size_t)Bn * Pn * Cn];   // only read by softmax repair
__device__ f16   g_kh[(size_t)Bn * Xn * Cn];
__device__ f16   g_kl[(size_t)Bn * Xn * Cn];   // only read by softmax repair
__device__ f16   g_v [(size_t)Bn * Xn * Cn];
__device__ f16   g_vt[(size_t)Bn * Cn * Xn];
__device__ float g_S [(size_t)Bn * Pn * Xn];   // scores fp32 (narrow repair band)
__device__ f16   g_W [(size_t)Bn * Pn * Xn];

// ---------------- PTX helpers ----------------
DI void cp_async16(uint32_t saddr, const void* gptr) {
    asm volatile("cp.async.cg.shared.global [%0], [%1], 16;\n" :: "r"(saddr), "l"(gptr));
}
DI void cp_commit() { asm volatile("cp.async.commit_group;\n"); }
template <int N> DI void cp_wait() { asm volatile("cp.async.wait_group %0;\n" :: "n"(N)); }

DI void ldsm4(uint32_t addr, uint32_t& r0, uint32_t& r1, uint32_t& r2, uint32_t& r3) {
    asm volatile("ldmatrix.sync.aligned.m8n8.x4.shared.b16 {%0,%1,%2,%3}, [%4];\n"
                 : "=r"(r0), "=r"(r1), "=r"(r2), "=r"(r3) : "r"(addr));
}
DI void mma16816(float c[4], const uint32_t a[4], const uint32_t b[2]) {
    asm volatile(
        "mma.sync.aligned.m16n8k16.row.col.f32.f16.f16.f32 "
        "{%0,%1,%2,%3}, {%4,%5,%6,%7}, {%8,%9}, {%0,%1,%2,%3};\n"
        : "+f"(c[0]), "+f"(c[1]), "+f"(c[2]), "+f"(c[3])
        : "r"(a[0]), "r"(a[1]), "r"(a[2]), "r"(a[3]), "r"(b[0]), "r"(b[1]));
}

// Swizzled byte offset inside a 128-row x 64-col f16 tile (128B rows, SW128 XOR).
DI uint32_t swz(int r, int c8) { return (uint32_t)(r * 128 + ((c8 ^ (r & 7)) << 4)); }

// ---------------- LayerNorm -> f16 (optionally hi/lo split), C = 1024 ----------------
__global__ void __launch_bounds__(256) ln_kernel(
    const float* __restrict__ src, f16* __restrict__ dst_h, f16* __restrict__ dst_l,
    const float* __restrict__ gamma, const float* __restrict__ beta,
    const float* __restrict__ cscale, float sconst)
{
    const int row = blockIdx.x;
    const int t = threadIdx.x;
    const float4* s4 = reinterpret_cast<const float4*>(src) + (size_t)row * 256;
    float4 x = s4[t];
    float sum = x.x + x.y + x.z + x.w;
    float sq  = fmaf(x.x, x.x, fmaf(x.y, x.y, fmaf(x.z, x.z, x.w * x.w)));
#pragma unroll
    for (int o = 16; o; o >>= 1) {
        sum += __shfl_xor_sync(0xffffffffu, sum, o);
        sq  += __shfl_xor_sync(0xffffffffu, sq,  o);
    }
    __shared__ float s_sum[8], s_sq[8];
    if ((t & 31) == 0) { s_sum[t >> 5] = sum; s_sq[t >> 5] = sq; }
    __syncthreads();
    sum = 0.f; sq = 0.f;
#pragma unroll
    for (int i = 0; i < 8; i++) { sum += s_sum[i]; sq += s_sq[i]; }
    const float mu  = sum * (1.f / 1024.f);
    const float var = sq * (1.f / 1024.f) - mu * mu;
    const float rs  = rsqrtf(var + 1e-5f);
    const float sc  = (cscale ? __ldg(cscale + row) : 1.f) * sconst;

    const float4 g = reinterpret_cast<const float4*>(gamma)[t];
    const float4 b = reinterpret_cast<const float4*>(beta)[t];
    float y[4];
    y[0] = ((x.x - mu) * rs * g.x + b.x) * sc;
    y[1] = ((x.y - mu) * rs * g.y + b.y) * sc;
    y[2] = ((x.z - mu) * rs * g.z + b.z) * sc;
    y[3] = ((x.w - mu) * rs * g.w + b.w) * sc;

    __half2 h01 = __floats2half2_rn(y[0], y[1]);
    __half2 h23 = __floats2half2_rn(y[2], y[3]);
    uint2 pk;
    pk.x = *reinterpret_cast<uint32_t*>(&h01);
    pk.y = *reinterpret_cast<uint32_t*>(&h23);
    reinterpret_cast<uint2*>(dst_h + (size_t)row * 1024)[t] = pk;

    if (dst_l) {
        float l0 = y[0] - __half2float(__low2half(h01));
        float l1 = y[1] - __half2float(__high2half(h01));
        float l2 = y[2] - __half2float(__low2half(h23));
        float l3 = y[3] - __half2float(__high2half(h23));
        __half2 l01 = __floats2half2_rn(l0, l1);
        __half2 l23 = __floats2half2_rn(l2, l3);
        uint2 pl;
        pl.x = *reinterpret_cast<uint32_t*>(&l01);
        pl.y = *reinterpret_cast<uint32_t*>(&l23);
        reinterpret_cast<uint2*>(dst_l + (size_t)row * 1024)[t] = pl;
    }
}

// ---------------- f16 transpose: [b][X][C] -> [b][C][X] ----------------
__global__ void transpose_kernel(const f16* __restrict__ src, f16* __restrict__ dst)
{
    __shared__ f16 tile[32][34];
    const int b = blockIdx.z;
    const int x0 = blockIdx.x << 5, c0 = blockIdx.y << 5;
    const f16* s = src + ((size_t)b * Xn + x0) * Cn + c0;
#pragma unroll
    for (int j = 0; j < 4; j++)
        tile[threadIdx.y + j * 8][threadIdx.x] =
            s[(size_t)(threadIdx.y + j * 8) * Cn + threadIdx.x];
    __syncthreads();
    f16* d = dst + ((size_t)b * Cn + c0) * Xn + x0;
#pragma unroll
    for (int j = 0; j < 4; j++)
        d[(size_t)(threadIdx.y + j * 8) * Xn + threadIdx.x] =
            tile[threadIdx.x][threadIdx.y + j * 8];
}

// ---------------- tiled f16 GEMM: 128x128 CTA tile, K-tiles of 64 ----------------
// Batched over blockIdx.z. EPI 0: store fp32 scores.  EPI 1: store fp32 (acc + Res).
template <int STAGES, int EPI>
__global__ void __launch_bounds__(256, 2) gemm_kernel(
    const f16* __restrict__ A0, const f16* __restrict__ B0,
    float* __restrict__ Co, const float* __restrict__ Res,
    int M, int N, int K)
{
    extern __shared__ __align__(1024) char smem_raw[];
    constexpr int TILE = 16384;                       // 128x64 f16
    constexpr int SS   = 2 * TILE;
    const int tid = threadIdx.x, lane = tid & 31, warp = tid >> 5;
    const int wm = warp & 3, wn = warp >> 2;          // 4 x 2 warp grid
    const int bN = blockIdx.x, bM = blockIdx.y, bz = blockIdx.z;

    const f16* Ap = A0 + (size_t)bz * M * K + (size_t)bM * 128 * K;
    const f16* Bp = B0 + (size_t)bz * N * K + (size_t)bN * 128 * K;

    const uint32_t sb = (uint32_t)__cvta_generic_to_shared(smem_raw);
    const int KT = K >> 6;

    auto fill = [&](int t) {
        const int k0 = t * 64;
        const uint32_t base = sb + (uint32_t)(t % STAGES) * SS;
#pragma unroll
        for (int i = 0; i < 4; i++) {
            int idx = tid + i * 256; int r = idx >> 3, c8 = idx & 7;
            cp_async16(base + swz(r, c8), Ap + (size_t)r * K + k0 + c8 * 8);
        }
#pragma unroll
        for (int i = 0; i < 4; i++) {
            int idx = tid + i * 256; int r = idx >> 3, c8 = idx & 7;
            cp_async16(base + TILE + swz(r, c8), Bp + (size_t)r * K + k0 + c8 * 8);
        }
        cp_commit();
    };

    float acc[2][8][4];
#pragma unroll
    for (int mt = 0; mt < 2; mt++)
#pragma unroll
        for (int nt = 0; nt < 8; nt++)
#pragma unroll
            for (int i = 0; i < 4; i++) acc[mt][nt][i] = 0.f;

#pragma unroll
    for (int t = 0; t < STAGES - 1; t++) fill(t);

    for (int kt = 0; kt < KT; kt++) {
        cp_wait<STAGES - 2>();
        __syncthreads();
        { const int t = kt + STAGES - 1; if (t < KT) fill(t); else cp_commit(); }

        const uint32_t base = sb + (uint32_t)(kt % STAGES) * SS;
        const uint32_t sA = base;
        const uint32_t sB = base + TILE;
#pragma unroll
        for (int kk = 0; kk < 4; kk++) {
            uint32_t bh[8][2];
#pragma unroll
            for (int np = 0; np < 4; np++) {
                int r = wn * 64 + np * 16 + ((lane >> 4) << 3) + (lane & 7);
                int c8 = kk * 2 + ((lane >> 3) & 1);
                ldsm4(sB + swz(r, c8), bh[2 * np][0], bh[2 * np][1],
                                        bh[2 * np + 1][0], bh[2 * np + 1][1]);
            }
            uint32_t ah[2][4];
#pragma unroll
            for (int mt = 0; mt < 2; mt++) {
                int r = wm * 32 + mt * 16 + (lane & 15);
                int c8 = kk * 2 + (lane >> 4);
                ldsm4(sA + swz(r, c8), ah[mt][0], ah[mt][1], ah[mt][2], ah[mt][3]);
            }
#pragma unroll
            for (int mt = 0; mt < 2; mt++)
#pragma unroll
                for (int nt = 0; nt < 8; nt++)
                    mma16816(acc[mt][nt], ah[mt], bh[nt]);
        }
    }

    const int row0 = bM * 128 + wm * 32;
    const int col0 = bN * 128 + wn * 64;
    const int tr = lane >> 2, tc = (lane & 3) << 1;
    float* C0 = Co + (size_t)bz * M * N;
    if (EPI == 0) {
#pragma unroll
        for (int mt = 0; mt < 2; mt++)
#pragma unroll
            for (int nt = 0; nt < 8; nt++) {
                int p = row0 + mt * 16 + tr, x = col0 + nt * 8 + tc;
                *reinterpret_cast<float2*>(C0 + (size_t)p * N + x) =
                    make_float2(acc[mt][nt][0], acc[mt][nt][1]);
                *reinterpret_cast<float2*>(C0 + (size_t)(p + 8) * N + x) =
                    make_float2(acc[mt][nt][2], acc[mt][nt][3]);
            }
    } else {
        const float* R0 = Res + (size_t)bz * M * N;
#pragma unroll
        for (int mt = 0; mt < 2; mt++)
#pragma unroll
            for (int nt = 0; nt < 8; nt++) {
                int p = row0 + mt * 16 + tr, x = col0 + nt * 8 + tc;
                float2 r0 = *reinterpret_cast<const float2*>(R0 + (size_t)p * N + x);
                float2 r1 = *reinterpret_cast<const float2*>(R0 + (size_t)(p + 8) * N + x);
                *reinterpret_cast<float2*>(C0 + (size_t)p * N + x) =
                    make_float2(acc[mt][nt][0] + r0.x, acc[mt][nt][1] + r0.y);
                *reinterpret_cast<float2*>(C0 + (size_t)(p + 8) * N + x) =
                    make_float2(acc[mt][nt][2] + r1.x, acc[mt][nt][3] + r1.y);
            }
    }
}

// ---------------- softmax (exp-domain) + near-threshold exact repair ----------------
DI float blockMax(float v, float* red) {
#pragma unroll
    for (int o = 16; o; o >>= 1) v = fmaxf(v, __shfl_xor_sync(0xffffffffu, v, o));
    __syncthreads();
    if ((threadIdx.x & 31) == 0) red[threadIdx.x >> 5] = v;
    __syncthreads();
    float r = red[0];
#pragma unroll
    for (int i = 1; i < 8; i++) r = fmaxf(r, red[i]);
    return r;
}
DI float blockSum(float v, float* red) {
#pragma unroll
    for (int o = 16; o; o >>= 1) v += __shfl_xor_sync(0xffffffffu, v, o);
    __syncthreads();
    if ((threadIdx.x & 31) == 0) red[threadIdx.x >> 5] = v;
    __syncthreads();
    float r = 0.f;
#pragma unroll
    for (int i = 0; i < 8; i++) r += red[i];
    return r;
}

constexpr int FCAP = 1024;

// All pointers are BASE pointers; addressing uses the global row.
__global__ void __launch_bounds__(256) softmax_kernel(
    const float* __restrict__ S,
    const f16* __restrict__ qh, const f16* __restrict__ ql,
    const f16* __restrict__ kh, const f16* __restrict__ kl,
    f16* __restrict__ W)
{
    __shared__ float red[8];
    __shared__ float q_s[1024];
    __shared__ int   nf;
    __shared__ int   fx[FCAP];
    __shared__ float fsn[FCAP];

    const int row = blockIdx.x;                // global row: b*Pn + p
    const int bz  = row >> 10;                 // Pn = 1024
    const int t = threadIdx.x;
    const int lane = t & 31, warp = t >> 5;

    // preload exact q row (qh+ql) to smem
    {
        const uint2 ph = reinterpret_cast<const uint2*>(qh + (size_t)row * 1024)[t];
        const uint2 pl = reinterpret_cast<const uint2*>(ql + (size_t)row * 1024)[t];
        __half2 h0 = *reinterpret_cast<const __half2*>(&ph.x);
        __half2 h1 = *reinterpret_cast<const __half2*>(&ph.y);
        __half2 l0 = *reinterpret_cast<const __half2*>(&pl.x);
        __half2 l1 = *reinterpret_cast<const __half2*>(&pl.y);
        q_s[4 * t + 0] = __low2float(h0)  + __low2float(l0);
        q_s[4 * t + 1] = __high2float(h0) + __high2float(l0);
        q_s[4 * t + 2] = __low2float(h1)  + __low2float(l1);
        q_s[4 * t + 3] = __high2float(h1) + __high2float(l1);
    }
    if (t == 0) nf = 0;

    // load fp32 scores: 8 x float4 = 32 values per thread
    const float4* s4 = reinterpret_cast<const float4*>(S + (size_t)row * Xn);
    float v[8][4];
    float m = -1e30f;
#pragma unroll
    for (int i = 0; i < 8; i++) {
        float4 vv = s4[t + i * 256];
        v[i][0] = vv.x; v[i][1] = vv.y; v[i][2] = vv.z; v[i][3] = vv.w;
        m = fmaxf(m, fmaxf(fmaxf(vv.x, vv.y), fmaxf(vv.z, vv.w)));
    }
    m = blockMax(m, red);                      // also fences q_s / nf writes

    // single exp pass: v becomes e = exp(s - m)
    float z = 0.f;
#pragma unroll
    for (int i = 0; i < 8; i++)
#pragma unroll
        for (int j = 0; j < 4; j++) { v[i][j] = __expf(v[i][j] - m); z += v[i][j]; }
    z = blockSum(z, red);

    // flag entries within +-2e-3 (log domain) of the approximate threshold
    // (fp32 scores: band only covers the fp16-operand GEMM error, ~12 sigma)
    const float ethr1 = 0.0005f * z;
    const float lo = ethr1 * 0.998002f;        // exp(-2e-3)
    const float hi = ethr1 * 1.002002f;        // exp(+2e-3)
#pragma unroll
    for (int i = 0; i < 8; i++)
#pragma unroll
        for (int j = 0; j < 4; j++) {
            if (v[i][j] > lo && v[i][j] < hi) {
                int sl = atomicAdd(&nf, 1);
                if (sl < FCAP) fx[sl] = 4 * (t + i * 256) + j;
            }
        }
    __syncthreads();
    const int nfc = min(nf, FCAP);

    // exact fp32 recompute of flagged scores: one warp per entry
    for (int e = warp; e < nfc; e += 8) {
        const int x = fx[e];
        const uint2* khp = reinterpret_cast<const uint2*>(kh + ((size_t)bz * Xn + x) * 1024);
        const uint2* klp = reinterpret_cast<const uint2*>(kl + ((size_t)bz * Xn + x) * 1024);
        float sum = 0.f;
#pragma unroll
        for (int jj = 0; jj < 8; jj++) {
            const int c4 = lane + jj * 32;
            const uint2 ph = khp[c4];
            const uint2 pl = klp[c4];
            __half2 h0 = *reinterpret_cast<const __half2*>(&ph.x);
            __half2 h1 = *reinterpret_cast<const __half2*>(&ph.y);
            __half2 l0 = *reinterpret_cast<const __half2*>(&pl.x);
            __half2 l1 = *reinterpret_cast<const __half2*>(&pl.y);
            sum = fmaf(q_s[4 * c4 + 0], __low2float(h0)  + __low2float(l0),  sum);
            sum = fmaf(q_s[4 * c4 + 1], __high2float(h0) + __high2float(l0), sum);
            sum = fmaf(q_s[4 * c4 + 2], __low2float(h1)  + __low2float(l1),  sum);
            sum = fmaf(q_s[4 * c4 + 3], __high2float(h1) + __high2float(l1), sum);
        }
#pragma unroll
        for (int o = 16; o; o >>= 1) sum += __shfl_xor_sync(0xffffffffu, sum, o);
        if (lane == 0) fsn[e] = __expf(sum - m);   // exact exp value
    }
    __syncthreads();

    // patch my registers with exact exp values
    for (int e = 0; e < nfc; e++) {
        const int x = fx[e];
        const int q4 = x >> 2;
        if ((q4 & 255) == t) v[q4 >> 8][x & 3] = fsn[e];
    }

    // rebuild Z and threshold from patched values (deterministic full reduction)
    float z_p = 0.f;
#pragma unroll
    for (int i = 0; i < 8; i++)
#pragma unroll
        for (int j = 0; j < 4; j++) z_p += v[i][j];
    z_p = blockSum(z_p, red);
    const float ethr = 0.0005f * z_p;

    float z2 = 0.f;
#pragma unroll
    for (int i = 0; i < 8; i++)
#pragma unroll
        for (int j = 0; j < 4; j++)
            if (v[i][j] >= ethr) z2 += v[i][j];
    z2 = blockSum(z2, red);
    const float inv = 1.f / z2;

    uint2* wo = reinterpret_cast<uint2*>(W + (size_t)row * Xn);
#pragma unroll
    for (int i = 0; i < 8; i++) {
        float w0 = (v[i][0] >= ethr) ? v[i][0] * inv : 0.f;
        float w1 = (v[i][1] >= ethr) ? v[i][1] * inv : 0.f;
        float w2 = (v[i][2] >= ethr) ? v[i][2] * inv : 0.f;
        float w3 = (v[i][3] >= ethr) ? v[i][3] * inv : 0.f;
        __half2 h01 = __floats2half2_rn(w0, w1);
        __half2 h23 = __floats2half2_rn(w2, w3);
        uint2 pk;
        pk.x = *reinterpret_cast<uint32_t*>(&h01);
        pk.y = *reinterpret_cast<uint32_t*>(&h23);
        wo[t + i * 256] = pk;
    }
}

// ---------------- launch (R8 topology: V-path fork only, monolithic GEMMs) ----------
extern "C" void kernel_launch(void* const* d_in, const int* in_sizes, int n_in,
                              void* d_out, int out_size)
{
    const float* feat  = (const float*)d_in[0];
    const float* mem_k = (const float*)d_in[1];
    const float* mem_v = (const float*)d_in[2];
    const float* mem_c = (const float*)d_in[3];
    // d_in[4] = mem_attn (unused by reference)
    const float* gq = (const float*)d_in[5];
    const float* bq = (const float*)d_in[6];
    const float* gk = (const float*)d_in[7];
    const float* bk = (const float*)d_in[8];
    const float* gv = (const float*)d_in[9];
    const float* bv = (const float*)d_in[10];
    float* out = (float*)d_out;

    f16 *qh, *ql, *kh, *kl, *v, *vt, *W;
    float* S;
    cudaGetSymbolAddress((void**)&qh, g_qh);
    cudaGetSymbolAddress((void**)&ql, g_ql);
    cudaGetSymbolAddress((void**)&kh, g_kh);
    cudaGetSymbolAddress((void**)&kl, g_kl);
    cudaGetSymbolAddress((void**)&v,  g_v);
    cudaGetSymbolAddress((void**)&vt, g_vt);
    cudaGetSymbolAddress((void**)&S,  g_S);
    cudaGetSymbolAddress((void**)&W,  g_W);

    // side stream + events, created once on the first (non-capturing) call
    static cudaStream_t s2 = nullptr;
    static cudaEvent_t evFork = nullptr, evJoin = nullptr;
    if (!s2) {
        cudaStreamCreateWithFlags(&s2, cudaStreamNonBlocking);
        cudaEventCreateWithFlags(&evFork, cudaEventDisableTiming);
        cudaEventCreateWithFlags(&evJoin, cudaEventDisableTiming);
    }

    // smem: 3 stages x 32KB = 98304 -> 2 CTAs/SM
    const int SM = 3 * 2 * 16384;
    cudaFuncSetAttribute(gemm_kernel<3, 0>, cudaFuncAttributeMaxDynamicSharedMemorySize, SM);
    cudaFuncSetAttribute(gemm_kernel<3, 1>, cudaFuncAttributeMaxDynamicSharedMemorySize, SM);

    // fork: V-path (ln_v + transpose) runs on the side stream
    cudaEventRecord(evFork, 0);
    cudaStreamWaitEvent(s2, evFork, 0);
    ln_kernel<<<Bn * Xn, 256, 0, s2>>>(mem_v, v, nullptr, gv, bv, nullptr, 1.f);
    transpose_kernel<<<dim3(Xn / 32, Cn / 32, Bn), dim3(32, 8), 0, s2>>>(v, vt);
    cudaEventRecord(evJoin, s2);

    // main path: LN for q and k
    ln_kernel<<<Bn * Pn, 256>>>(feat,  qh, ql, gq, bq, nullptr, S32);
    ln_kernel<<<Bn * Xn, 256>>>(mem_k, kh, kl, gk, bk, mem_c,   S32);

    // S~ = qh @ kh^T  (single fp16 pass, fp32 scores; repaired in softmax)
    gemm_kernel<3, 0><<<dim3(Xn / 128, Pn / 128, Bn), 256, SM>>>(
        qh, kh, S, nullptr, Pn, Xn, Cn);

    softmax_kernel<<<Bn * Pn, 256>>>(S, qh, ql, kh, kl, W);

    // join: GEMM2 needs vt from the side stream
    cudaStreamWaitEvent(0, evJoin, 0);

    // out = W @ v^T + feat
    gemm_kernel<3, 1><<<dim3(Cn / 128, Pn / 128, Bn), 256, SM>>>(
        W, vt, out, feat, Pn, Cn, Xn);
}

// round 14
// speedup vs baseline: 1.9018x; 1.2842x over previous
#include <cuda_runtime.h>
#include <cuda_fp16.h>
#include <cstdint>
#include <cstddef>

typedef __half f16;
#define DI __device__ __forceinline__

constexpr int Bn = 4, Pn = 1024, Xn = 8192, Cn = 1024;
// symmetric fold: q *= S32, k *= c * S32  ->  q.k carries 1/32 = 1/sqrt(C)
#define S32 0.1767766952966369f

// ---------------- scratch (device globals, no allocation) ----------------
__device__ f16   g_qh[(size_t)Bn * Pn * Cn];
__device__ f16   g_ql[(size_t)Bn * Pn * Cn];   // only read by repair
__device__ f16   g_kh[(size_t)Bn * Xn * Cn];
__device__ f16   g_kl[(size_t)Bn * Xn * Cn];   // only read by repair
__device__ f16   g_v [(size_t)Bn * Xn * Cn];
__device__ float g_S [(size_t)Bn * Pn * Xn];   // scores fp32

// ---------------- PTX helpers ----------------
DI void cp_async16(uint32_t saddr, const void* gptr) {
    asm volatile("cp.async.cg.shared.global [%0], [%1], 16;\n" :: "r"(saddr), "l"(gptr));
}
DI void cp_commit() { asm volatile("cp.async.commit_group;\n"); }
template <int N> DI void cp_wait() { asm volatile("cp.async.wait_group %0;\n" :: "n"(N)); }

DI void ldsm4(uint32_t addr, uint32_t& r0, uint32_t& r1, uint32_t& r2, uint32_t& r3) {
    asm volatile("ldmatrix.sync.aligned.m8n8.x4.shared.b16 {%0,%1,%2,%3}, [%4];\n"
                 : "=r"(r0), "=r"(r1), "=r"(r2), "=r"(r3) : "r"(addr));
}
DI void mma16816(float c[4], const uint32_t a[4], const uint32_t b[2]) {
    asm volatile(
        "mma.sync.aligned.m16n8k16.row.col.f32.f16.f16.f32 "
        "{%0,%1,%2,%3}, {%4,%5,%6,%7}, {%8,%9}, {%0,%1,%2,%3};\n"
        : "+f"(c[0]), "+f"(c[1]), "+f"(c[2]), "+f"(c[3])
        : "r"(a[0]), "r"(a[1]), "r"(a[2]), "r"(a[3]), "r"(b[0]), "r"(b[1]));
}

// Swizzled byte offset inside a 128-row x 64-col f16 tile (128B rows, SW128 XOR).
DI uint32_t swz(int r, int c8) { return (uint32_t)(r * 128 + ((c8 ^ (r & 7)) << 4)); }

// ---------------- LayerNorm -> f16 (optionally hi/lo split), C = 1024 ----------------
__global__ void __launch_bounds__(256) ln_kernel(
    const float* __restrict__ src, f16* __restrict__ dst_h, f16* __restrict__ dst_l,
    const float* __restrict__ gamma, const float* __restrict__ beta,
    const float* __restrict__ cscale, float sconst)
{
    const int row = blockIdx.x;
    const int t = threadIdx.x;
    const float4* s4 = reinterpret_cast<const float4*>(src) + (size_t)row * 256;
    float4 x = s4[t];
    float sum = x.x + x.y + x.z + x.w;
    float sq  = fmaf(x.x, x.x, fmaf(x.y, x.y, fmaf(x.z, x.z, x.w * x.w)));
#pragma unroll
    for (int o = 16; o; o >>= 1) {
        sum += __shfl_xor_sync(0xffffffffu, sum, o);
        sq  += __shfl_xor_sync(0xffffffffu, sq,  o);
    }
    __shared__ float s_sum[8], s_sq[8];
    if ((t & 31) == 0) { s_sum[t >> 5] = sum; s_sq[t >> 5] = sq; }
    __syncthreads();
    sum = 0.f; sq = 0.f;
#pragma unroll
    for (int i = 0; i < 8; i++) { sum += s_sum[i]; sq += s_sq[i]; }
    const float mu  = sum * (1.f / 1024.f);
    const float var = sq * (1.f / 1024.f) - mu * mu;
    const float rs  = rsqrtf(var + 1e-5f);
    const float sc  = (cscale ? __ldg(cscale + row) : 1.f) * sconst;

    const float4 g = reinterpret_cast<const float4*>(gamma)[t];
    const float4 b = reinterpret_cast<const float4*>(beta)[t];
    float y[4];
    y[0] = ((x.x - mu) * rs * g.x + b.x) * sc;
    y[1] = ((x.y - mu) * rs * g.y + b.y) * sc;
    y[2] = ((x.z - mu) * rs * g.z + b.z) * sc;
    y[3] = ((x.w - mu) * rs * g.w + b.w) * sc;

    __half2 h01 = __floats2half2_rn(y[0], y[1]);
    __half2 h23 = __floats2half2_rn(y[2], y[3]);
    uint2 pk;
    pk.x = *reinterpret_cast<uint32_t*>(&h01);
    pk.y = *reinterpret_cast<uint32_t*>(&h23);
    reinterpret_cast<uint2*>(dst_h + (size_t)row * 1024)[t] = pk;

    if (dst_l) {
        float l0 = y[0] - __half2float(__low2half(h01));
        float l1 = y[1] - __half2float(__high2half(h01));
        float l2 = y[2] - __half2float(__low2half(h23));
        float l3 = y[3] - __half2float(__high2half(h23));
        __half2 l01 = __floats2half2_rn(l0, l1);
        __half2 l23 = __floats2half2_rn(l2, l3);
        uint2 pl;
        pl.x = *reinterpret_cast<uint32_t*>(&l01);
        pl.y = *reinterpret_cast<uint32_t*>(&l23);
        reinterpret_cast<uint2*>(dst_l + (size_t)row * 1024)[t] = pl;
    }
}

// ---------------- tiled f16 GEMM (GEMM1 only): 128x128 CTA tile, fp32 out ----------
template <int STAGES>
__global__ void __launch_bounds__(256, 2) gemm_kernel(
    const f16* __restrict__ A0, const f16* __restrict__ B0,
    float* __restrict__ Co, int M, int N, int K)
{
    extern __shared__ __align__(1024) char smem_raw[];
    constexpr int TILE = 16384;                       // 128x64 f16
    constexpr int SS   = 2 * TILE;
    const int tid = threadIdx.x, lane = tid & 31, warp = tid >> 5;
    const int wm = warp & 3, wn = warp >> 2;          // 4 x 2 warp grid
    const int bN = blockIdx.x, bM = blockIdx.y, bz = blockIdx.z;

    const f16* Ap = A0 + (size_t)bz * M * K + (size_t)bM * 128 * K;
    const f16* Bp = B0 + (size_t)bz * N * K + (size_t)bN * 128 * K;

    const uint32_t sb = (uint32_t)__cvta_generic_to_shared(smem_raw);
    const int KT = K >> 6;

    auto fill = [&](int t) {
        const int k0 = t * 64;
        const uint32_t base = sb + (uint32_t)(t % STAGES) * SS;
#pragma unroll
        for (int i = 0; i < 4; i++) {
            int idx = tid + i * 256; int r = idx >> 3, c8 = idx & 7;
            cp_async16(base + swz(r, c8), Ap + (size_t)r * K + k0 + c8 * 8);
        }
#pragma unroll
        for (int i = 0; i < 4; i++) {
            int idx = tid + i * 256; int r = idx >> 3, c8 = idx & 7;
            cp_async16(base + TILE + swz(r, c8), Bp + (size_t)r * K + k0 + c8 * 8);
        }
        cp_commit();
    };

    float acc[2][8][4];
#pragma unroll
    for (int mt = 0; mt < 2; mt++)
#pragma unroll
        for (int nt = 0; nt < 8; nt++)
#pragma unroll
            for (int i = 0; i < 4; i++) acc[mt][nt][i] = 0.f;

#pragma unroll
    for (int t = 0; t < STAGES - 1; t++) fill(t);

    for (int kt = 0; kt < KT; kt++) {
        cp_wait<STAGES - 2>();
        __syncthreads();
        { const int t = kt + STAGES - 1; if (t < KT) fill(t); else cp_commit(); }

        const uint32_t base = sb + (uint32_t)(kt % STAGES) * SS;
        const uint32_t sA = base;
        const uint32_t sB = base + TILE;
#pragma unroll
        for (int kk = 0; kk < 4; kk++) {
            uint32_t bh[8][2];
#pragma unroll
            for (int np = 0; np < 4; np++) {
                int r = wn * 64 + np * 16 + ((lane >> 4) << 3) + (lane & 7);
                int c8 = kk * 2 + ((lane >> 3) & 1);
                ldsm4(sB + swz(r, c8), bh[2 * np][0], bh[2 * np][1],
                                        bh[2 * np + 1][0], bh[2 * np + 1][1]);
            }
            uint32_t ah[2][4];
#pragma unroll
            for (int mt = 0; mt < 2; mt++) {
                int r = wm * 32 + mt * 16 + (lane & 15);
                int c8 = kk * 2 + (lane >> 4);
                ldsm4(sA + swz(r, c8), ah[mt][0], ah[mt][1], ah[mt][2], ah[mt][3]);
            }
#pragma unroll
            for (int mt = 0; mt < 2; mt++)
#pragma unroll
                for (int nt = 0; nt < 8; nt++)
                    mma16816(acc[mt][nt], ah[mt], bh[nt]);
        }
    }

    const int row0 = bM * 128 + wm * 32;
    const int col0 = bN * 128 + wn * 64;
    const int tr = lane >> 2, tc = (lane & 3) << 1;
    float* C0 = Co + (size_t)bz * M * N;
#pragma unroll
    for (int mt = 0; mt < 2; mt++)
#pragma unroll
        for (int nt = 0; nt < 8; nt++) {
            int p = row0 + mt * 16 + tr, x = col0 + nt * 8 + tc;
            *reinterpret_cast<float2*>(C0 + (size_t)p * N + x) =
                make_float2(acc[mt][nt][0], acc[mt][nt][1]);
            *reinterpret_cast<float2*>(C0 + (size_t)(p + 8) * N + x) =
                make_float2(acc[mt][nt][2], acc[mt][nt][3]);
        }
}

// ---------------- fused softmax + repair + sparse SpMM + residual ----------------
DI float blockMax(float v, float* red) {
#pragma unroll
    for (int o = 16; o; o >>= 1) v = fmaxf(v, __shfl_xor_sync(0xffffffffu, v, o));
    __syncthreads();
    if ((threadIdx.x & 31) == 0) red[threadIdx.x >> 5] = v;
    __syncthreads();
    float r = red[0];
#pragma unroll
    for (int i = 1; i < 8; i++) r = fmaxf(r, red[i]);
    return r;
}
DI float blockSum(float v, float* red) {
#pragma unroll
    for (int o = 16; o; o >>= 1) v += __shfl_xor_sync(0xffffffffu, v, o);
    __syncthreads();
    if ((threadIdx.x & 31) == 0) red[threadIdx.x >> 5] = v;
    __syncthreads();
    float r = 0.f;
#pragma unroll
    for (int i = 0; i < 8; i++) r += red[i];
    return r;
}

constexpr int FCAP = 1024;

__global__ void __launch_bounds__(256) softmax_spmm_kernel(
    const float* __restrict__ S,
    const f16* __restrict__ qh, const f16* __restrict__ ql,
    const f16* __restrict__ kh, const f16* __restrict__ kl,
    const f16* __restrict__ V, const float* __restrict__ feat,
    float* __restrict__ out)
{
    __shared__ float red[8];
    __shared__ float q_s[1024];
    __shared__ int   nf;
    __shared__ int   fx[FCAP];
    __shared__ float fsn[FCAP];
    __shared__ int   sidx[1024];
    __shared__ float sval[1024];
    __shared__ int   wtot[8], wbase[8], s_total;

    const int row = blockIdx.x;                // global row: b*Pn + p
    const int bz  = row >> 10;                 // Pn = 1024
    const int t = threadIdx.x;
    const int lane = t & 31, warp = t >> 5;

    // preload exact q row (qh+ql) to smem
    {
        const uint2 ph = reinterpret_cast<const uint2*>(qh + (size_t)row * 1024)[t];
        const uint2 pl = reinterpret_cast<const uint2*>(ql + (size_t)row * 1024)[t];
        __half2 h0 = *reinterpret_cast<const __half2*>(&ph.x);
        __half2 h1 = *reinterpret_cast<const __half2*>(&ph.y);
        __half2 l0 = *reinterpret_cast<const __half2*>(&pl.x);
        __half2 l1 = *reinterpret_cast<const __half2*>(&pl.y);
        q_s[4 * t + 0] = __low2float(h0)  + __low2float(l0);
        q_s[4 * t + 1] = __high2float(h0) + __high2float(l0);
        q_s[4 * t + 2] = __low2float(h1)  + __low2float(l1);
        q_s[4 * t + 3] = __high2float(h1) + __high2float(l1);
    }
    if (t == 0) nf = 0;

    // load fp32 scores: 8 x float4 = 32 values per thread
    const float4* s4 = reinterpret_cast<const float4*>(S + (size_t)row * Xn);
    float v[8][4];
    float m = -1e30f;
#pragma unroll
    for (int i = 0; i < 8; i++) {
        float4 vv = s4[t + i * 256];
        v[i][0] = vv.x; v[i][1] = vv.y; v[i][2] = vv.z; v[i][3] = vv.w;
        m = fmaxf(m, fmaxf(fmaxf(vv.x, vv.y), fmaxf(vv.z, vv.w)));
    }
    m = blockMax(m, red);                      // also fences q_s / nf writes

    // single exp pass: v becomes e = exp(s - m)
    float z = 0.f;
#pragma unroll
    for (int i = 0; i < 8; i++)
#pragma unroll
        for (int j = 0; j < 4; j++) { v[i][j] = __expf(v[i][j] - m); z += v[i][j]; }
    z = blockSum(z, red);

    // flag entries within +-2e-3 (log domain) of the approximate threshold
    const float ethr1 = 0.0005f * z;
    const float lo = ethr1 * 0.998002f;        // exp(-2e-3)
    const float hi = ethr1 * 1.002002f;        // exp(+2e-3)
#pragma unroll
    for (int i = 0; i < 8; i++)
#pragma unroll
        for (int j = 0; j < 4; j++) {
            if (v[i][j] > lo && v[i][j] < hi) {
                int sl = atomicAdd(&nf, 1);
                if (sl < FCAP) fx[sl] = 4 * (t + i * 256) + j;
            }
        }
    __syncthreads();
    const int nfc = min(nf, FCAP);

    // exact fp32 recompute of flagged scores: one warp per entry
    for (int e = warp; e < nfc; e += 8) {
        const int x = fx[e];
        const uint2* khp = reinterpret_cast<const uint2*>(kh + ((size_t)bz * Xn + x) * 1024);
        const uint2* klp = reinterpret_cast<const uint2*>(kl + ((size_t)bz * Xn + x) * 1024);
        float sum = 0.f;
#pragma unroll
        for (int jj = 0; jj < 8; jj++) {
            const int c4 = lane + jj * 32;
            const uint2 ph = khp[c4];
            const uint2 pl = klp[c4];
            __half2 h0 = *reinterpret_cast<const __half2*>(&ph.x);
            __half2 h1 = *reinterpret_cast<const __half2*>(&ph.y);
            __half2 l0 = *reinterpret_cast<const __half2*>(&pl.x);
            __half2 l1 = *reinterpret_cast<const __half2*>(&pl.y);
            sum = fmaf(q_s[4 * c4 + 0], __low2float(h0)  + __low2float(l0),  sum);
            sum = fmaf(q_s[4 * c4 + 1], __high2float(h0) + __high2float(l0), sum);
            sum = fmaf(q_s[4 * c4 + 2], __low2float(h1)  + __low2float(l1),  sum);
            sum = fmaf(q_s[4 * c4 + 3], __high2float(h1) + __high2float(l1), sum);
        }
#pragma unroll
        for (int o = 16; o; o >>= 1) sum += __shfl_xor_sync(0xffffffffu, sum, o);
        if (lane == 0) fsn[e] = __expf(sum - m);   // exact exp value
    }
    __syncthreads();

    // patch my registers with exact exp values
    for (int e = 0; e < nfc; e++) {
        const int x = fx[e];
        const int q4 = x >> 2;
        if ((q4 & 255) == t) v[q4 >> 8][x & 3] = fsn[e];
    }

    // rebuild Z and threshold from patched values (deterministic full reduction)
    float z_p = 0.f;
#pragma unroll
    for (int i = 0; i < 8; i++)
#pragma unroll
        for (int j = 0; j < 4; j++) z_p += v[i][j];
    z_p = blockSum(z_p, red);
    const float ethr = 0.0005f * z_p;

    float z2 = 0.f;
#pragma unroll
    for (int i = 0; i < 8; i++)
#pragma unroll
        for (int j = 0; j < 4; j++)
            if (v[i][j] >= ethr) z2 += v[i][j];
    z2 = blockSum(z2, red);
    const float inv = 1.f / z2;

    // ---- sparse SpMM: out = feat + inv * sum_{survivors} e_x * V[x, :] ----
    const f16* vb = V + (size_t)bz * Xn * 1024;
    float a0 = 0.f, a1 = 0.f, a2 = 0.f, a3 = 0.f;

    for (int i = 0; i < 8; i++) {
        // survivor mask among my 4 entries of this chunk
        int msk = 0;
#pragma unroll
        for (int j = 0; j < 4; j++) if (v[i][j] >= ethr) msk |= (1 << j);
        int cnt = __popc((unsigned)msk);

        // deterministic compaction: warp inclusive scan + block scan of warp totals
        unsigned inc = (unsigned)cnt;
#pragma unroll
        for (int o = 1; o < 32; o <<= 1) {
            unsigned xx = __shfl_up_sync(0xffffffffu, inc, o);
            if (lane >= o) inc += xx;
        }
        if (lane == 31) wtot[warp] = (int)inc;
        __syncthreads();
        if (t == 0) {
            int s = 0;
#pragma unroll
            for (int w = 0; w < 8; w++) { wbase[w] = s; s += wtot[w]; }
            s_total = s;
        }
        __syncthreads();
        int pos = wbase[warp] + (int)inc - cnt;
#pragma unroll
        for (int j = 0; j < 4; j++) {
            if (msk & (1 << j)) {
                sidx[pos] = 4 * (t + i * 256) + j;
                sval[pos] = v[i][j];
                pos++;
            }
        }
        __syncthreads();
        const int sc = s_total;

        // accumulate survivors: coalesced 2KB gathers of V rows
        for (int e = 0; e < sc; e++) {
            const int x = sidx[e];
            const float w = sval[e];
            const uint2 pv = *reinterpret_cast<const uint2*>(vb + (size_t)x * 1024 + 4 * t);
            __half2 h0 = *reinterpret_cast<const __half2*>(&pv.x);
            __half2 h1 = *reinterpret_cast<const __half2*>(&pv.y);
            float2 f0 = __half22float2(h0);
            float2 f1 = __half22float2(h1);
            a0 = fmaf(w, f0.x, a0);
            a1 = fmaf(w, f0.y, a1);
            a2 = fmaf(w, f1.x, a2);
            a3 = fmaf(w, f1.y, a3);
        }
        __syncthreads();   // protect sidx/sval/wtot for next chunk
    }

    const float4 fr = *reinterpret_cast<const float4*>(feat + (size_t)row * 1024 + 4 * t);
    float4 o4;
    o4.x = fr.x + inv * a0;
    o4.y = fr.y + inv * a1;
    o4.z = fr.z + inv * a2;
    o4.w = fr.w + inv * a3;
    *reinterpret_cast<float4*>(out + (size_t)row * 1024 + 4 * t) = o4;
}

// ---------------- launch ----------------
extern "C" void kernel_launch(void* const* d_in, const int* in_sizes, int n_in,
                              void* d_out, int out_size)
{
    const float* feat  = (const float*)d_in[0];
    const float* mem_k = (const float*)d_in[1];
    const float* mem_v = (const float*)d_in[2];
    const float* mem_c = (const float*)d_in[3];
    // d_in[4] = mem_attn (unused by reference)
    const float* gq = (const float*)d_in[5];
    const float* bq = (const float*)d_in[6];
    const float* gk = (const float*)d_in[7];
    const float* bk = (const float*)d_in[8];
    const float* gv = (const float*)d_in[9];
    const float* bv = (const float*)d_in[10];
    float* out = (float*)d_out;

    f16 *qh, *ql, *kh, *kl, *v;
    float* S;
    cudaGetSymbolAddress((void**)&qh, g_qh);
    cudaGetSymbolAddress((void**)&ql, g_ql);
    cudaGetSymbolAddress((void**)&kh, g_kh);
    cudaGetSymbolAddress((void**)&kl, g_kl);
    cudaGetSymbolAddress((void**)&v,  g_v);
    cudaGetSymbolAddress((void**)&S,  g_S);

    // side stream + events, created once on the first (non-capturing) call
    static cudaStream_t s2 = nullptr;
    static cudaEvent_t evFork = nullptr, evJoin = nullptr;
    if (!s2) {
        cudaStreamCreateWithFlags(&s2, cudaStreamNonBlocking);
        cudaEventCreateWithFlags(&evFork, cudaEventDisableTiming);
        cudaEventCreateWithFlags(&evJoin, cudaEventDisableTiming);
    }

    // smem: 3 stages x 32KB = 98304 -> 2 CTAs/SM
    const int SM = 3 * 2 * 16384;
    cudaFuncSetAttribute(gemm_kernel<3>, cudaFuncAttributeMaxDynamicSharedMemorySize, SM);

    // fork: V-path (ln_v only — no transpose needed anymore) on the side stream
    cudaEventRecord(evFork, 0);
    cudaStreamWaitEvent(s2, evFork, 0);
    ln_kernel<<<Bn * Xn, 256, 0, s2>>>(mem_v, v, nullptr, gv, bv, nullptr, 1.f);
    cudaEventRecord(evJoin, s2);

    // main path: LN for q and k
    ln_kernel<<<Bn * Pn, 256>>>(feat,  qh, ql, gq, bq, nullptr, S32);
    ln_kernel<<<Bn * Xn, 256>>>(mem_k, kh, kl, gk, bk, mem_c,   S32);

    // S~ = qh @ kh^T  (single fp16 pass, fp32 scores; repaired in fused kernel)
    gemm_kernel<3><<<dim3(Xn / 128, Pn / 128, Bn), 256, SM>>>(
        qh, kh, S, Pn, Xn, Cn);

    // join: fused kernel reads v from the side stream
    cudaStreamWaitEvent(0, evJoin, 0);

    // fused: softmax + threshold repair + sparse SpMM + residual -> out
    softmax_spmm_kernel<<<Bn * Pn, 256>>>(S, qh, ql, kh, kl, v, feat, out);
}